// round 15
// baseline (speedup 1.0000x reference)
#include <cuda_runtime.h>
#include <cstdint>

#define NB 16
#define TT 128
#define VV 64
#define FF 16
#define TBL 4                    // timesteps per CTA
#define NTB (TT / TBL)           // 32 t-blocks (= slices)
#define NK 32                    // k-offsets (pairs (i, i+k), k=1..32)
#define PADF 20                  // padded feature stride (80B, 16B-aligned)
#define TSTRIDE (VV * PADF * 4)  // 5120 B per timestep plane

// scratch[slice][n][k-1][i]  (32*16*32*64 floats = 4 MB)
__device__ __align__(16) float g_part[NTB * NB * NK * VV];
// arrival counters per n (zero-init; finalizer resets -> graph-replay safe)
__device__ int g_cnt[NB];

__device__ __forceinline__ int prow(int r) {      // parity swizzle
    r &= 63;
    return (r >> 1) + ((r & 1) << 5);
}

__device__ __forceinline__ uint32_t smem_u32(const void* p) {
    uint32_t a;
    asm("{ .reg .u64 t; cvta.to.shared.u64 t, %1; cvt.u32.u64 %0, t; }"
        : "=r"(a) : "l"(p));
    return a;
}

// 16B shared load at immediate offset, directly into two u64 regs.
#define LDS2(LO, HI, AD, OFF)                                              \
    asm("ld.shared.v2.u64 {%0,%1}, [%2+" OFF "];"                          \
        : "=l"(LO), "=l"(HI) : "r"(AD))

// Load one 64B feature row (8 packed f32x2) from smem address AD.
#define LDROW(J, AD)                                                       \
    LDS2((J)[0], (J)[1], AD, "0");  LDS2((J)[2], (J)[3], AD, "16");        \
    LDS2((J)[4], (J)[5], AD, "32"); LDS2((J)[6], (J)[7], AD, "48")

// acc += af * |zi - zj|   (packed f32x2; abs = clear both sign bits)
__device__ __forceinline__ void step(uint64_t& acc, uint64_t zi, uint64_t zj,
                                     uint64_t af) {
    uint64_t d;
    asm("sub.rn.f32x2 %0, %1, %2;" : "=l"(d) : "l"(zi), "l"(zj));
    d &= 0x7FFFFFFF7FFFFFFFULL;
    asm("fma.rn.f32x2 %0, %1, %2, %3;"
        : "=l"(acc) : "l"(af), "l"(d), "l"(acc));
}

__device__ __forceinline__ void group(uint64_t& acc, const uint64_t* zi,
                                      const uint64_t* zj, const uint64_t* af) {
#pragma unroll
    for (int p = 0; p < 8; p++) step(acc, zi[p], zj[p], af[p]);
}

// ---------------------------------------------------------------------------
// Fused kernel: tight codegen (R13) x true 24 warps/SM x all SMs.
// 256 thr = 128 pair-threads x 2 t-slots (2 timesteps each); thread owns
// i-rows {i0,i0+1} x k in (k0,k0+8]. Grid 32x16 = 512 CTAs at 3 CTAs/SM
// (20KB smem, <=85 regs) -> 444-CTA wave + backfill. Last CTA per n finalizes.
// ---------------------------------------------------------------------------
__global__ __launch_bounds__(256, 3) void gl_fused_kernel(
    const float* __restrict__ x, const float* __restrict__ a,
    float* __restrict__ out)
{
    __shared__ __align__(16) float tile[TBL * VV * PADF];   // 20 KB (reused)
    __shared__ int isLast;

    const int n   = blockIdx.y;
    const int tb  = blockIdx.x;
    const int tid = threadIdx.x;
    const int q    = tid & 127;       // pair-thread id
    const int slot = tid >> 7;        // t-slot 0/1
    const int i0   = (q & 31) * 2;    // even base vertex
    const int k0   = (q >> 5) * 8;    // k-group base (0,8,16,24)

    // Load tile: x[n, tb*4 : +4, :, :] contiguous (4096 floats).
    const float4* src = (const float4*)(x + (size_t)(n * TT + tb * TBL) * VV * FF);
#pragma unroll
    for (int w = tid; w < TBL * VV * 4; w += 256) {
        float4 v = src[w];
        int t  = w >> 8;
        int r  = w & 255;
        int vv = r >> 2;
        int f4 = r & 3;
        *(float4*)&tile[((size_t)t * VV + prow(vv)) * PADF + f4 * 4] = v;
    }

    // Pack a[f] pairs into f32x2 regs (low 32 bits = even f).
    uint64_t af2[8];
#pragma unroll
    for (int k = 0; k < 8; k++) {
        af2[k] = (uint64_t)__float_as_uint(__ldg(&a[2 * k])) |
                 ((uint64_t)__float_as_uint(__ldg(&a[2 * k + 1])) << 32);
    }
    __syncthreads();

    // Precompute smem byte offsets (loop-invariant across t).
    const uint32_t tbase = smem_u32(tile);
    const uint32_t offI0 = (uint32_t)((i0 >> 1) * PADF) * 4;
    const uint32_t offI1 = (uint32_t)(((i0 >> 1) + 32) * PADF) * 4;
    uint32_t offJ[9];
#pragma unroll
    for (int r = 0; r < 9; r++)
        offJ[r] = (uint32_t)(prow(i0 + k0 + r + 1) * PADF) * 4;

    uint64_t accA[8], accB[8];
#pragma unroll
    for (int d = 0; d < 8; d++) { accA[d] = 0ull; accB[d] = 0ull; }

#pragma unroll 1
    for (int tt = 0; tt < 2; tt++) {
        const uint32_t base = tbase + (uint32_t)(slot * 2 + tt) * TSTRIDE;

        // i-rows (no negation needed with sub2).
        uint64_t zi0[8], zi1[8];
        LDROW(zi0, base + offI0);
        LDROW(zi1, base + offI1);

        // Software-pipelined j-rows: prefetch r+1 before computing r.
        uint64_t jb[2][8];
        LDROW(jb[0], base + offJ[0]);
#pragma unroll
        for (int r = 1; r <= 9; r++) {
            const int cur = (r - 1) & 1;
            const int nxt = r & 1;
            if (r < 9) { LDROW(jb[nxt], base + offJ[r]); }
            if (r <= 8) group(accA[r - 1], zi0, jb[cur], af2);
            if (r >= 2) group(accB[r - 2], zi1, jb[cur], af2);
        }
    }

    // Reduce packed halves to scalar.
    float sA[8], sB[8];
#pragma unroll
    for (int d = 0; d < 8; d++) {
        sA[d] = __uint_as_float((unsigned)accA[d]) +
                __uint_as_float((unsigned)(accA[d] >> 32));
        sB[d] = __uint_as_float((unsigned)accB[d]) +
                __uint_as_float((unsigned)(accB[d] >> 32));
    }

    // Combine the 2 t-slots in (reused) smem: slot 1 writes, slot 0 sums.
    __syncthreads();
    float* red = tile;                // 128 x 16 floats = 8 KB
    if (slot == 1) {
#pragma unroll
        for (int d = 0; d < 8; d++) {
            red[(q * 2 + 0) * 8 + d] = sA[d];
            red[(q * 2 + 1) * 8 + d] = sB[d];
        }
    }
    __syncthreads();
    if (slot == 0) {
        float* outp = &g_part[(((size_t)tb * NB + n) * NK + k0) * VV + i0];
#pragma unroll
        for (int d = 0; d < 8; d++) {
            float2 w;
            w.x = sA[d] + red[(q * 2 + 0) * 8 + d];
            w.y = sB[d] + red[(q * 2 + 1) * 8 + d];
            *(float2*)(outp + (size_t)d * VV) = w;    // [k-1][i0..i0+1]
        }
    }

    // ---- Last-block finalize for this n ----
    __threadfence();
    __syncthreads();
    if (tid == 0) {
        int old = atomicAdd(&g_cnt[n], 1);
        isLast = (old == NTB - 1);
    }
    __syncthreads();
    if (!isLast) return;

    float (*E)[VV + 2] = (float (*)[VV + 2])tile;     // reuse smem (16.9 KB)
    float* cinv = tile + VV * (VV + 2);

    {   // Phase A: reduce 32 slices at 2 positions/thread (batched MLP-8).
        const float4* g4 = (const float4*)g_part;
        const int ss   = NB * NK * VV / 4;            // 8192 float4 / slice
        const int base = n * (NK * VV / 4);           // n*512
        float4 s0 = make_float4(0.f, 0.f, 0.f, 0.f);
        float4 s1 = make_float4(0.f, 0.f, 0.f, 0.f);
#pragma unroll
        for (int sl = 0; sl < NTB; sl += 4) {
            float4 a0 = g4[(size_t)(sl + 0) * ss + base + tid];
            float4 a1 = g4[(size_t)(sl + 1) * ss + base + tid];
            float4 a2 = g4[(size_t)(sl + 2) * ss + base + tid];
            float4 a3 = g4[(size_t)(sl + 3) * ss + base + tid];
            float4 b0 = g4[(size_t)(sl + 0) * ss + base + 256 + tid];
            float4 b1 = g4[(size_t)(sl + 1) * ss + base + 256 + tid];
            float4 b2 = g4[(size_t)(sl + 2) * ss + base + 256 + tid];
            float4 b3 = g4[(size_t)(sl + 3) * ss + base + 256 + tid];
            s0.x += (a0.x + a1.x) + (a2.x + a3.x);
            s0.y += (a0.y + a1.y) + (a2.y + a3.y);
            s0.z += (a0.z + a1.z) + (a2.z + a3.z);
            s0.w += (a0.w + a1.w) + (a2.w + a3.w);
            s1.x += (b0.x + b1.x) + (b2.x + b3.x);
            s1.y += (b0.y + b1.y) + (b2.y + b3.y);
            s1.z += (b0.z + b1.z) + (b2.z + b3.z);
            s1.w += (b0.w + b1.w) + (b2.w + b3.w);
        }
        const float inv = 1.0f / (float)TT;
        float4 sv[2] = {s0, s1};
#pragma unroll
        for (int b = 0; b < 2; b++) {
            int pos   = tid + b * 256;
            int k_act = (pos >> 4) + 1;               // k (1..32)
            int ia    = (pos & 15) * 4;
            float ev[4] = { expf(fmaxf(sv[b].x * inv, 0.f)),
                            expf(fmaxf(sv[b].y * inv, 0.f)),
                            expf(fmaxf(sv[b].z * inv, 0.f)),
                            expf(fmaxf(sv[b].w * inv, 0.f)) };
#pragma unroll
            for (int p = 0; p < 4; p++) {
                int ii = ia + p;
                int jj = (ii + k_act) & 63;
                E[ii][jj] = ev[p];
                E[jj][ii] = ev[p];
            }
        }
        if (tid < VV) E[tid][tid] = 1.0f;             // diag: exp(relu(0))
    }
    __syncthreads();

    {   // Phase B: column sums over i (8 warps x 8 columns each).
        const int w = tid >> 5, lane = tid & 31;
#pragma unroll
        for (int c = 0; c < 8; c++) {
            int j = w * 8 + c;
            float v = E[lane][j] + E[lane + 32][j];
#pragma unroll
            for (int o = 16; o; o >>= 1) v += __shfl_xor_sync(0xffffffffu, v, o);
            if (lane == 0) cinv[j] = 1.0f / v;
        }
    }
    __syncthreads();

    {   // Phase C: out[n][i][jb..jb+15] = E[i][.] * cinv[.], 4x float4.
        const int i  = tid >> 2;
        const int jb = (tid & 3) * 16;
        float* o = out + (size_t)n * VV * VV + i * VV + jb;
#pragma unroll
        for (int g = 0; g < 4; g++) {
            float4 w;
            w.x = E[i][jb + g * 4 + 0] * cinv[jb + g * 4 + 0];
            w.y = E[i][jb + g * 4 + 1] * cinv[jb + g * 4 + 1];
            w.z = E[i][jb + g * 4 + 2] * cinv[jb + g * 4 + 2];
            w.w = E[i][jb + g * 4 + 3] * cinv[jb + g * 4 + 3];
            *(float4*)(o + g * 4) = w;
        }
    }

    if (tid == 0) g_cnt[n] = 0;       // reset for next graph replay
}

extern "C" void kernel_launch(void* const* d_in, const int* in_sizes, int n_in,
                              void* d_out, int out_size)
{
    const float* x = (const float*)d_in[0];       // [16,128,64,16] fp32
    const float* a = (const float*)d_in[1];       // [16,1] fp32
    float* out = (float*)d_out;                   // [16,64,64] fp32

    gl_fused_kernel<<<dim3(NTB, NB), 256>>>(x, a, out);
}

// round 16
// speedup vs baseline: 1.1278x; 1.1278x over previous
#include <cuda_runtime.h>
#include <cstdint>

#define NB 16
#define TT 128
#define VV 64
#define FF 16
#define TBL 8                    // timesteps per CTA
#define NTB (TT / TBL)           // 16 t-blocks (= slices)
#define NK 32                    // k-offsets (pairs (i, i+k), k=1..32)
#define PADF 20                  // padded feature stride (80B, 16B-aligned)

// scratch[slice][n][k-1][i]  (16*16*32*64 floats = 2 MB)
__device__ __align__(16) float g_part[NTB * NB * NK * VV];
// arrival counters per n (zero-init; finalizer resets -> graph-replay safe)
__device__ int g_cnt[NB];

// Parity swizzle: even logical rows -> physical 0..31, odd -> 32..63.
__device__ __forceinline__ int prow(int r) {
    r &= 63;
    return (r >> 1) + ((r & 1) << 5);
}

// ---------------------------------------------------------------------------
// Fused kernel = R8's proven-fastest mainloop (TBL=8, 256 thr, loose codegen,
// launch_bounds(256,2), regs<=128, 2 CTAs/SM) + last-block finalize.
// partial[tb][n][k-1][i] = sum_{8 t, 16 f} a[f] * |x[t,i,f] - x[t,(i+k)%64,f]|
// 256 thr = 128 pair-threads x 2 t-slots (4 timesteps each); thread owns
// i-rows {i0, i0+1} and k = k0+1..k0+8 (9 j-row loads serve 16 pairs).
// The 16th CTA to finish a given n reduces the 16 slices (L2-hot), applies
// exp(relu(mean)), expands symmetric, column-normalizes, stores out[n,:,:].
// ---------------------------------------------------------------------------
__global__ __launch_bounds__(256, 2) void gl_fused_kernel(
    const float* __restrict__ x, const float* __restrict__ a,
    float* __restrict__ out)
{
    __shared__ __align__(16) float tile[TBL][VV][PADF];   // 40 KB (reused)
    __shared__ int isLast;

    const int n   = blockIdx.y;
    const int tb  = blockIdx.x;
    const int tid = threadIdx.x;
    const int q    = tid & 127;       // pair-thread id
    const int slot = tid >> 7;        // t-slot 0/1
    const int i0   = (q & 31) * 2;    // even base vertex
    const int k0   = (q >> 5) * 8;    // k-group base (0,8,16,24)

    // Load tile: x[n, tb*8 : +8, :, :] contiguous (8192 floats).
    const float4* src = (const float4*)(x + (size_t)(n * TT + tb * TBL) * VV * FF);
#pragma unroll
    for (int w = tid; w < TBL * VV * 4; w += 256) {
        float4 v = src[w];
        int t  = w >> 8;
        int r  = w & 255;
        int vv = r >> 2;
        int f4 = r & 3;
        *(float4*)&tile[t][prow(vv)][f4 * 4] = v;
    }

    // Pack a[f] pairs into f32x2 (low 32 bits = even f).
    uint64_t af2[8];
#pragma unroll
    for (int k = 0; k < 8; k++) {
        af2[k] = (uint64_t)__float_as_uint(__ldg(&a[2 * k])) |
                 ((uint64_t)__float_as_uint(__ldg(&a[2 * k + 1])) << 32);
    }
    __syncthreads();

    uint64_t acc[2][8];
#pragma unroll
    for (int m = 0; m < 2; m++)
#pragma unroll
        for (int d = 0; d < 8; d++) acc[m][d] = 0ull;

#pragma unroll 1
    for (int tt = 0; tt < 4; tt++) {
        const int t = slot * 4 + tt;
        // i-rows (phys: i0>>1 and i0>>1 + 32), negated for add2-based sub.
        uint64_t nzi[2][8];
#pragma unroll
        for (int m = 0; m < 2; m++) {
            const ulonglong2* zr =
                (const ulonglong2*)&tile[t][(i0 >> 1) + m * 32][0];
            ulonglong2 z0 = zr[0], z1 = zr[1], z2 = zr[2], z3 = zr[3];
            nzi[m][0] = z0.x ^ 0x8000000080000000ULL;
            nzi[m][1] = z0.y ^ 0x8000000080000000ULL;
            nzi[m][2] = z1.x ^ 0x8000000080000000ULL;
            nzi[m][3] = z1.y ^ 0x8000000080000000ULL;
            nzi[m][4] = z2.x ^ 0x8000000080000000ULL;
            nzi[m][5] = z2.y ^ 0x8000000080000000ULL;
            nzi[m][6] = z3.x ^ 0x8000000080000000ULL;
            nzi[m][7] = z3.y ^ 0x8000000080000000ULL;
        }

#pragma unroll
        for (int r = 1; r <= 9; r++) {
            const ulonglong2* zjr =
                (const ulonglong2*)&tile[t][prow(i0 + k0 + r)][0];
            ulonglong2 w0 = zjr[0], w1 = zjr[1], w2 = zjr[2], w3 = zjr[3];
            uint64_t zj[8] = {w0.x, w0.y, w1.x, w1.y, w2.x, w2.y, w3.x, w3.y};
            if (r <= 8) {             // pair (i0, i0+k0+r) -> acc[0][r-1]
#pragma unroll
                for (int p = 0; p < 8; p++) {
                    uint64_t d;
                    asm("add.rn.f32x2 %0, %1, %2;"
                        : "=l"(d) : "l"(nzi[0][p]), "l"(zj[p]));
                    d &= 0x7FFFFFFF7FFFFFFFULL;
                    asm("fma.rn.f32x2 %0, %1, %2, %3;"
                        : "=l"(acc[0][r - 1]) : "l"(af2[p]), "l"(d), "l"(acc[0][r - 1]));
                }
            }
            if (r >= 2) {             // pair (i0+1, i0+k0+r) -> acc[1][r-2]
#pragma unroll
                for (int p = 0; p < 8; p++) {
                    uint64_t d;
                    asm("add.rn.f32x2 %0, %1, %2;"
                        : "=l"(d) : "l"(nzi[1][p]), "l"(zj[p]));
                    d &= 0x7FFFFFFF7FFFFFFFULL;
                    asm("fma.rn.f32x2 %0, %1, %2, %3;"
                        : "=l"(acc[1][r - 2]) : "l"(af2[p]), "l"(d), "l"(acc[1][r - 2]));
                }
            }
        }
    }

    // Reduce packed halves to scalar per (m,d).
    float s[2][8];
#pragma unroll
    for (int m = 0; m < 2; m++)
#pragma unroll
        for (int d = 0; d < 8; d++)
            s[m][d] = __uint_as_float((unsigned)acc[m][d]) +
                      __uint_as_float((unsigned)(acc[m][d] >> 32));

    // Combine the two t-slots in (reused) smem, then slot 0 stores.
    __syncthreads();
    float* red = (float*)tile;
    if (slot == 1) {
#pragma unroll
        for (int m = 0; m < 2; m++)
#pragma unroll
            for (int d = 0; d < 8; d++)
                red[q * 16 + m * 8 + d] = s[m][d];
    }
    __syncthreads();
    if (slot == 0) {
        float* outp = &g_part[(((size_t)tb * NB + n) * NK + k0) * VV + i0];
#pragma unroll
        for (int d = 0; d < 8; d++) {
            float2 w;
            w.x = s[0][d] + red[q * 16 + d];
            w.y = s[1][d] + red[q * 16 + 8 + d];
            *(float2*)(outp + (size_t)d * VV) = w;    // [k-1][i0..i0+1]
        }
    }

    // ---- Last-block finalize for this n ----
    __threadfence();
    __syncthreads();
    if (tid == 0) {
        int old = atomicAdd(&g_cnt[n], 1);
        isLast = (old == NTB - 1);
    }
    __syncthreads();
    if (!isLast) return;

    float (*E)[VV + 2] = (float (*)[VV + 2])tile;     // reuse smem (16.9 KB)
    float* cinv = ((float*)tile) + VV * (VV + 2);

    {   // Phase A: reduce 16 slices at 2 positions/thread (batched MLP-8).
        const float4* g4 = (const float4*)g_part;
        const int ss   = NB * NK * VV / 4;            // 8192 float4 / slice
        const int base = n * (NK * VV / 4);           // n*512
        float4 s0 = make_float4(0.f, 0.f, 0.f, 0.f);
        float4 s1 = make_float4(0.f, 0.f, 0.f, 0.f);
#pragma unroll
        for (int sl = 0; sl < NTB; sl += 4) {
            float4 a0 = g4[(size_t)(sl + 0) * ss + base + tid];
            float4 a1 = g4[(size_t)(sl + 1) * ss + base + tid];
            float4 a2 = g4[(size_t)(sl + 2) * ss + base + tid];
            float4 a3 = g4[(size_t)(sl + 3) * ss + base + tid];
            float4 b0 = g4[(size_t)(sl + 0) * ss + base + 256 + tid];
            float4 b1 = g4[(size_t)(sl + 1) * ss + base + 256 + tid];
            float4 b2 = g4[(size_t)(sl + 2) * ss + base + 256 + tid];
            float4 b3 = g4[(size_t)(sl + 3) * ss + base + 256 + tid];
            s0.x += (a0.x + a1.x) + (a2.x + a3.x);
            s0.y += (a0.y + a1.y) + (a2.y + a3.y);
            s0.z += (a0.z + a1.z) + (a2.z + a3.z);
            s0.w += (a0.w + a1.w) + (a2.w + a3.w);
            s1.x += (b0.x + b1.x) + (b2.x + b3.x);
            s1.y += (b0.y + b1.y) + (b2.y + b3.y);
            s1.z += (b0.z + b1.z) + (b2.z + b3.z);
            s1.w += (b0.w + b1.w) + (b2.w + b3.w);
        }
        const float inv = 1.0f / (float)TT;
        float4 sv[2] = {s0, s1};
#pragma unroll
        for (int b = 0; b < 2; b++) {
            int pos   = tid + b * 256;
            int k_act = (pos >> 4) + 1;               // k (1..32)
            int ia    = (pos & 15) * 4;
            float ev[4] = { expf(fmaxf(sv[b].x * inv, 0.f)),
                            expf(fmaxf(sv[b].y * inv, 0.f)),
                            expf(fmaxf(sv[b].z * inv, 0.f)),
                            expf(fmaxf(sv[b].w * inv, 0.f)) };
#pragma unroll
            for (int p = 0; p < 4; p++) {
                int ii = ia + p;
                int jj = (ii + k_act) & 63;
                E[ii][jj] = ev[p];
                E[jj][ii] = ev[p];
            }
        }
        if (tid < VV) E[tid][tid] = 1.0f;             // diag: exp(relu(0))
    }
    __syncthreads();

    {   // Phase B: column sums over i (8 warps x 8 columns each).
        const int w = tid >> 5, lane = tid & 31;
#pragma unroll
        for (int c = 0; c < 8; c++) {
            int j = w * 8 + c;
            float v = E[lane][j] + E[lane + 32][j];
#pragma unroll
            for (int o = 16; o; o >>= 1) v += __shfl_xor_sync(0xffffffffu, v, o);
            if (lane == 0) cinv[j] = 1.0f / v;
        }
    }
    __syncthreads();

    {   // Phase C: out[n][i][jb..jb+15] = E[i][.] * cinv[.], 4x float4.
        const int i  = tid >> 2;
        const int jb = (tid & 3) * 16;
        float* o = out + (size_t)n * VV * VV + i * VV + jb;
#pragma unroll
        for (int g = 0; g < 4; g++) {
            float4 w;
            w.x = E[i][jb + g * 4 + 0] * cinv[jb + g * 4 + 0];
            w.y = E[i][jb + g * 4 + 1] * cinv[jb + g * 4 + 1];
            w.z = E[i][jb + g * 4 + 2] * cinv[jb + g * 4 + 2];
            w.w = E[i][jb + g * 4 + 3] * cinv[jb + g * 4 + 3];
            *(float4*)(o + g * 4) = w;
        }
    }

    if (tid == 0) g_cnt[n] = 0;       // reset for next graph replay
}

extern "C" void kernel_launch(void* const* d_in, const int* in_sizes, int n_in,
                              void* d_out, int out_size)
{
    const float* x = (const float*)d_in[0];       // [16,128,64,16] fp32
    const float* a = (const float*)d_in[1];       // [16,1] fp32
    float* out = (float*)d_out;                   // [16,64,64] fp32

    gl_fused_kernel<<<dim3(NTB, NB), 256>>>(x, a, out);
}

// round 17
// speedup vs baseline: 1.3371x; 1.1856x over previous
#include <cuda_runtime.h>
#include <cstdint>

#define NB 16
#define TT 128
#define VV 64
#define FF 16
#define TBL 16                   // timesteps per CTA
#define NTB (TT / TBL)           // 8 t-blocks (= slices)
#define NK 32                    // k-offsets (pairs (i, i+k), k=1..32)
#define PADF 20                  // padded feature stride (80B, 16B-aligned)
#define TSTRIDE (VV * PADF * 4)  // 5120 B per timestep plane
#define K1_SMEM (TBL * VV * PADF * 4)   // 81920 B

// scratch[slice][n][k-1][i]  (8*16*32*64 floats = 1 MB)
__device__ __align__(16) float g_part[NTB * NB * NK * VV];
// arrival counters per n (zero-init; finalizer resets -> graph-replay safe)
__device__ int g_cnt[NB];

__device__ __forceinline__ int prow(int r) {      // parity swizzle
    r &= 63;
    return (r >> 1) + ((r & 1) << 5);
}

__device__ __forceinline__ uint32_t smem_u32(const void* p) {
    uint32_t a;
    asm("{ .reg .u64 t; cvta.to.shared.u64 t, %1; cvt.u32.u64 %0, t; }"
        : "=r"(a) : "l"(p));
    return a;
}

// 16B shared load at immediate offset, directly into two u64 regs.
#define LDS2(LO, HI, AD, OFF)                                              \
    asm("ld.shared.v2.u64 {%0,%1}, [%2+" OFF "];"                          \
        : "=l"(LO), "=l"(HI) : "r"(AD))

// Load one 64B feature row (8 packed f32x2) from smem address AD.
#define LDROW(J, AD)                                                       \
    LDS2((J)[0], (J)[1], AD, "0");  LDS2((J)[2], (J)[3], AD, "16");        \
    LDS2((J)[4], (J)[5], AD, "32"); LDS2((J)[6], (J)[7], AD, "48")

// Tile holds y = |a_f| * x.  Per step (2 features):
//   u   = y_i - y_j                       (sub2, fma pipe, rt2)
//   v   = (u & 0x7FFFFFFF) ^ sx           (one LOP3 per half: abs + sign(a_f))
//   acc = acc + v                         (add2, fma pipe, rt2)
// where sx has 0x80000000 in halves whose a_f < 0, so v = sign(a_f)*|a_f d_f|.
__device__ __forceinline__ void step(uint64_t& acc, uint64_t zi, uint64_t zj,
                                     uint64_t sx) {
    uint64_t u;
    asm("sub.rn.f32x2 %0, %1, %2;" : "=l"(u) : "l"(zi), "l"(zj));
    u = (u & 0x7FFFFFFF7FFFFFFFULL) ^ sx;             // 2x LOP3 (3-input)
    asm("add.rn.f32x2 %0, %1, %2;" : "=l"(acc) : "l"(acc), "l"(u));
}

__device__ __forceinline__ void group(uint64_t& acc, const uint64_t* zi,
                                      const uint64_t* zj, const uint64_t* sx) {
#pragma unroll
    for (int p = 0; p < 8; p++) step(acc, zi[p], zj[p], sx[p]);
}

// ---------------------------------------------------------------------------
// Fused kernel = R13 champion structure + prescaled tile (no per-step FMA2).
// 512 thr = 128 pair-threads x 4 t-slots; thread owns i-rows {i0,i0+1} x
// k in (k0,k0+8]. Grid 8x16 = 128 CTAs = one wave. Last CTA per n finalizes.
// ---------------------------------------------------------------------------
__global__ __launch_bounds__(512, 1) void gl_fused_kernel(
    const float* __restrict__ x, const float* __restrict__ a,
    float* __restrict__ out)
{
    extern __shared__ __align__(16) float tile[];   // [TBL][VV][PADF] = 80 KB
    __shared__ int isLast;

    const int n   = blockIdx.y;
    const int tb  = blockIdx.x;
    const int tid = threadIdx.x;
    const int q    = tid & 127;       // pair-thread id
    const int slot = tid >> 7;        // t-slot 0..3
    const int i0   = (q & 31) * 2;    // even base vertex
    const int k0   = (q >> 5) * 8;    // k-group base (0,8,16,24)

    // a-quad for this thread's fill column (f4 = tid&3, constant per thread).
    const float4* a4 = (const float4*)a;
    float4 a0 = __ldg(&a4[0]), a1 = __ldg(&a4[1]);
    float4 a2 = __ldg(&a4[2]), a3 = __ldg(&a4[3]);
    const int myf4 = tid & 3;
    float4 am = (myf4 == 0) ? a0 : (myf4 == 1) ? a1 : (myf4 == 2) ? a2 : a3;
    float4 aabs;                      // |a_f| for prescale
    aabs.x = fabsf(am.x); aabs.y = fabsf(am.y);
    aabs.z = fabsf(am.z); aabs.w = fabsf(am.w);

    // Load tile prescaled: y = |a_f| * x[n, tb*16 : +16, :, :].
    const float4* src = (const float4*)(x + (size_t)(n * TT + tb * TBL) * VV * FF);
#pragma unroll
    for (int w = tid; w < TBL * VV * 4; w += 512) {
        float4 v = src[w];                            // (w&3) == tid&3 always
        v.x *= aabs.x; v.y *= aabs.y; v.z *= aabs.z; v.w *= aabs.w;
        int t  = w >> 8;
        int r  = w & 255;
        int vv = r >> 2;
        *(float4*)&tile[((size_t)t * VV + prow(vv)) * PADF + myf4 * 4] = v;
    }

    // Per-feature-pair sign constants: 0x80000000 in halves where a_f < 0.
    uint64_t sx[8];
#pragma unroll
    for (int k = 0; k < 8; k++) {
        uint32_t lo = (__ldg(&a[2 * k])     < 0.f) ? 0x80000000u : 0u;
        uint32_t hi = (__ldg(&a[2 * k + 1]) < 0.f) ? 0x80000000u : 0u;
        sx[k] = (uint64_t)lo | ((uint64_t)hi << 32);
    }
    __syncthreads();

    // Precompute smem byte offsets (loop-invariant across t).
    const uint32_t tbase = smem_u32(tile);
    const uint32_t offI0 = (uint32_t)((i0 >> 1) * PADF) * 4;
    const uint32_t offI1 = (uint32_t)(((i0 >> 1) + 32) * PADF) * 4;
    uint32_t offJ[9];
#pragma unroll
    for (int r = 0; r < 9; r++)
        offJ[r] = (uint32_t)(prow(i0 + k0 + r + 1) * PADF) * 4;

    uint64_t accA[8], accB[8];
#pragma unroll
    for (int d = 0; d < 8; d++) { accA[d] = 0ull; accB[d] = 0ull; }

#pragma unroll 1
    for (int tt = 0; tt < 4; tt++) {
        const uint32_t base = tbase + (uint32_t)(slot * 4 + tt) * TSTRIDE;

        uint64_t zi0[8], zi1[8];
        LDROW(zi0, base + offI0);
        LDROW(zi1, base + offI1);

        // Software-pipelined j-rows: prefetch r+1 before computing r.
        uint64_t jb[2][8];
        LDROW(jb[0], base + offJ[0]);
#pragma unroll
        for (int r = 1; r <= 9; r++) {
            const int cur = (r - 1) & 1;
            const int nxt = r & 1;
            if (r < 9) { LDROW(jb[nxt], base + offJ[r]); }
            if (r <= 8) group(accA[r - 1], zi0, jb[cur], sx);
            if (r >= 2) group(accB[r - 2], zi1, jb[cur], sx);
        }
    }

    // Reduce packed halves to scalar.
    float sA[8], sB[8];
#pragma unroll
    for (int d = 0; d < 8; d++) {
        sA[d] = __uint_as_float((unsigned)accA[d]) +
                __uint_as_float((unsigned)(accA[d] >> 32));
        sB[d] = __uint_as_float((unsigned)accB[d]) +
                __uint_as_float((unsigned)(accB[d] >> 32));
    }

    // Combine the 4 t-slots in (reused) smem: slots 1..3 write, slot 0 sums.
    __syncthreads();
    float* red = tile;                // 3 * 128 * 16 floats = 24 KB
    if (slot > 0) {
#pragma unroll
        for (int d = 0; d < 8; d++) {
            red[(((slot - 1) * 128 + q) * 2 + 0) * 8 + d] = sA[d];
            red[(((slot - 1) * 128 + q) * 2 + 1) * 8 + d] = sB[d];
        }
    }
    __syncthreads();
    if (slot == 0) {
        float* outp = &g_part[(((size_t)tb * NB + n) * NK + k0) * VV + i0];
#pragma unroll
        for (int d = 0; d < 8; d++) {
            float2 w;
            w.x = sA[d] + red[(q * 2 + 0) * 8 + d]
                        + red[((128 + q) * 2 + 0) * 8 + d]
                        + red[((256 + q) * 2 + 0) * 8 + d];
            w.y = sB[d] + red[(q * 2 + 1) * 8 + d]
                        + red[((128 + q) * 2 + 1) * 8 + d]
                        + red[((256 + q) * 2 + 1) * 8 + d];
            *(float2*)(outp + (size_t)d * VV) = w;    // [k-1][i0..i0+1]
        }
    }

    // ---- Last-block finalize for this n ----
    __threadfence();
    __syncthreads();
    if (tid == 0) {
        int old = atomicAdd(&g_cnt[n], 1);
        isLast = (old == NTB - 1);
    }
    __syncthreads();
    if (!isLast) return;

    float (*E)[VV + 2] = (float (*)[VV + 2])tile;     // reuse smem
    float* cinv = tile + VV * (VV + 2);

    {   // Phase A: reduce 8 slices (L2-hot), e = exp(relu(mean)), scatter.
        const float4* g4 = (const float4*)g_part;
        const int base = n * (NK * VV / 4) + tid;
        const int ss   = NB * NK * VV / 4;
        float4 v0 = g4[(size_t)0 * ss + base];
        float4 v1 = g4[(size_t)1 * ss + base];
        float4 v2 = g4[(size_t)2 * ss + base];
        float4 v3 = g4[(size_t)3 * ss + base];
        float4 v4 = g4[(size_t)4 * ss + base];
        float4 v5 = g4[(size_t)5 * ss + base];
        float4 v6 = g4[(size_t)6 * ss + base];
        float4 v7 = g4[(size_t)7 * ss + base];
        float4 sv;
        sv.x = ((v0.x + v1.x) + (v2.x + v3.x)) + ((v4.x + v5.x) + (v6.x + v7.x));
        sv.y = ((v0.y + v1.y) + (v2.y + v3.y)) + ((v4.y + v5.y) + (v6.y + v7.y));
        sv.z = ((v0.z + v1.z) + (v2.z + v3.z)) + ((v4.z + v5.z) + (v6.z + v7.z));
        sv.w = ((v0.w + v1.w) + (v2.w + v3.w)) + ((v4.w + v5.w) + (v6.w + v7.w));

        const float inv = 1.0f / (float)TT;
        const int k_act = (tid >> 4) + 1;
        const int ia    = (tid & 15) * 4;
        float ev[4] = { expf(fmaxf(sv.x * inv, 0.f)), expf(fmaxf(sv.y * inv, 0.f)),
                        expf(fmaxf(sv.z * inv, 0.f)), expf(fmaxf(sv.w * inv, 0.f)) };
#pragma unroll
        for (int p = 0; p < 4; p++) {
            int ii = ia + p;
            int jj = (ii + k_act) & 63;
            E[ii][jj] = ev[p];
            E[jj][ii] = ev[p];
        }
        if (tid < VV) E[tid][tid] = 1.0f;             // diag: exp(relu(0))
    }
    __syncthreads();

    {   // Phase B: column sums over i (16 warps x 4 columns).
        const int w = tid >> 5, lane = tid & 31;
#pragma unroll
        for (int c = 0; c < 4; c++) {
            int j = w * 4 + c;
            float v = E[lane][j] + E[lane + 32][j];
#pragma unroll
            for (int o = 16; o; o >>= 1) v += __shfl_xor_sync(0xffffffffu, v, o);
            if (lane == 0) cinv[j] = 1.0f / v;
        }
    }
    __syncthreads();

    {   // Phase C: out[n][i][j] = E[i][j] * cinv[j], 2x float4 stores.
        const int i  = tid >> 3;
        const int jb2 = (tid & 7) * 8;
        float4 w0, w1;
        w0.x = E[i][jb2 + 0] * cinv[jb2 + 0];
        w0.y = E[i][jb2 + 1] * cinv[jb2 + 1];
        w0.z = E[i][jb2 + 2] * cinv[jb2 + 2];
        w0.w = E[i][jb2 + 3] * cinv[jb2 + 3];
        w1.x = E[i][jb2 + 4] * cinv[jb2 + 4];
        w1.y = E[i][jb2 + 5] * cinv[jb2 + 5];
        w1.z = E[i][jb2 + 6] * cinv[jb2 + 6];
        w1.w = E[i][jb2 + 7] * cinv[jb2 + 7];
        float* o = out + (size_t)n * VV * VV + i * VV + jb2;
        *(float4*)o       = w0;
        *(float4*)(o + 4) = w1;
    }

    if (tid == 0) g_cnt[n] = 0;       // reset for next graph replay
}

extern "C" void kernel_launch(void* const* d_in, const int* in_sizes, int n_in,
                              void* d_out, int out_size)
{
    const float* x = (const float*)d_in[0];       // [16,128,64,16] fp32
    const float* a = (const float*)d_in[1];       // [16,1] fp32
    float* out = (float*)d_out;                   // [16,64,64] fp32

    cudaFuncSetAttribute(gl_fused_kernel,
                         cudaFuncAttributeMaxDynamicSharedMemorySize, K1_SMEM);
    gl_fused_kernel<<<dim3(NTB, NB), 512, K1_SMEM>>>(x, a, out);
}